// round 1
// baseline (speedup 1.0000x reference)
#include <cuda_runtime.h>

#define N_NODES 100000
#define IN_DIM 128
#define HIDDEN 64

// Scratch (allocation-guard-safe: __device__ globals)
__device__ float g_weights[N_NODES];
__device__ float g_readout[(size_t)N_NODES * IN_DIM];

// ---------------------------------------------------------------------------
// Kernel 1: per-node gate  weights[n] = sigmoid(tanh(x@W_sim+b_sim)@w_vec+b_vec)
// ---------------------------------------------------------------------------
__global__ void gate_kernel(const float* __restrict__ x,
                            const float* __restrict__ W_sim,
                            const float* __restrict__ b_sim,
                            const float* __restrict__ w_vec,
                            const float* __restrict__ b_vec,
                            int N) {
    __shared__ float Ws[IN_DIM * HIDDEN];   // 32 KB
    __shared__ float bs[HIDDEN];
    __shared__ float wv[HIDDEN];
    __shared__ float bv;
    for (int i = threadIdx.x; i < IN_DIM * HIDDEN; i += blockDim.x) Ws[i] = W_sim[i];
    for (int i = threadIdx.x; i < HIDDEN; i += blockDim.x) { bs[i] = b_sim[i]; wv[i] = w_vec[i]; }
    if (threadIdx.x == 0) bv = b_vec[0];
    __syncthreads();

    int n = blockIdx.x * blockDim.x + threadIdx.x;
    if (n >= N) return;

    float acc[HIDDEN];
#pragma unroll
    for (int h = 0; h < HIDDEN; h++) acc[h] = bs[h];

    const float4* xr = reinterpret_cast<const float4*>(x) + (size_t)n * (IN_DIM / 4);
#pragma unroll 4
    for (int k4 = 0; k4 < IN_DIM / 4; k4++) {
        float4 v = xr[k4];
        float xv[4] = {v.x, v.y, v.z, v.w};
        int k = k4 * 4;
#pragma unroll
        for (int kk = 0; kk < 4; kk++) {
            const float4* wrow = reinterpret_cast<const float4*>(Ws + (k + kk) * HIDDEN);
            float xs = xv[kk];
#pragma unroll
            for (int h4 = 0; h4 < HIDDEN / 4; h4++) {
                float4 w = wrow[h4];
                acc[h4 * 4 + 0] = fmaf(xs, w.x, acc[h4 * 4 + 0]);
                acc[h4 * 4 + 1] = fmaf(xs, w.y, acc[h4 * 4 + 1]);
                acc[h4 * 4 + 2] = fmaf(xs, w.z, acc[h4 * 4 + 2]);
                acc[h4 * 4 + 3] = fmaf(xs, w.w, acc[h4 * 4 + 3]);
            }
        }
    }

    float z = bv;
#pragma unroll
    for (int h = 0; h < HIDDEN; h++) z = fmaf(tanhf(acc[h]), wv[h], z);
    g_weights[n] = 1.0f / (1.0f + expf(-z));
}

// ---------------------------------------------------------------------------
// Kernel 2: zero the readout accumulator (graph replays must be deterministic)
// ---------------------------------------------------------------------------
__global__ void zero_kernel(size_t n4) {
    size_t i = (size_t)blockIdx.x * blockDim.x + threadIdx.x;
    if (i < n4) reinterpret_cast<float4*>(g_readout)[i] = make_float4(0.f, 0.f, 0.f, 0.f);
}

// ---------------------------------------------------------------------------
// Kernel 3: scatter  readout[row] += x[col] * weights[col]   (warp per edge)
// ---------------------------------------------------------------------------
__device__ __forceinline__ void red_add_v4(float* addr, float4 v) {
    asm volatile("red.global.add.v4.f32 [%0], {%1,%2,%3,%4};"
                 :: "l"(addr), "f"(v.x), "f"(v.y), "f"(v.z), "f"(v.w)
                 : "memory");
}

__global__ void scatter_kernel(const float* __restrict__ x,
                               const int* __restrict__ ei,   // [2, E] int32
                               long long E) {
    long long w = (long long)blockIdx.x * (blockDim.x >> 5) + (threadIdx.x >> 5);
    if (w >= E) return;
    int lane = threadIdx.x & 31;
    int row = ei[w];        // destination
    int col = ei[E + w];    // source
    float g = g_weights[col];
    float4 v = reinterpret_cast<const float4*>(x)[(size_t)col * (IN_DIM / 4) + lane];
    v.x *= g; v.y *= g; v.z *= g; v.w *= g;
    float* dst = g_readout + (size_t)row * IN_DIM + lane * 4;
    red_add_v4(dst, v);
}

// ---------------------------------------------------------------------------
// Kernel 4: out = x + relu(readout@W1+b1)@W2 + b2
// ---------------------------------------------------------------------------
__global__ void mlp_kernel(const float* __restrict__ x,
                           const float* __restrict__ W1,
                           const float* __restrict__ b1,
                           const float* __restrict__ W2,
                           const float* __restrict__ b2,
                           float* __restrict__ out, int N) {
    extern __shared__ float smem[];
    float* W1s = smem;                 // 8192 floats
    float* W2s = smem + 8192;          // 8192 floats
    float* b1s = smem + 16384;         // 64
    float* b2s = smem + 16448;         // 128
    for (int i = threadIdx.x; i < 8192; i += blockDim.x) { W1s[i] = W1[i]; W2s[i] = W2[i]; }
    for (int i = threadIdx.x; i < HIDDEN; i += blockDim.x) b1s[i] = b1[i];
    for (int i = threadIdx.x; i < IN_DIM; i += blockDim.x) b2s[i] = b2[i];
    __syncthreads();

    int n = blockIdx.x * blockDim.x + threadIdx.x;
    if (n >= N) return;

    // stage 1: h = relu(readout @ W1 + b1)
    float h[HIDDEN];
#pragma unroll
    for (int j = 0; j < HIDDEN; j++) h[j] = b1s[j];

    const float4* rr = reinterpret_cast<const float4*>(g_readout) + (size_t)n * (IN_DIM / 4);
#pragma unroll 4
    for (int k4 = 0; k4 < IN_DIM / 4; k4++) {
        float4 v = rr[k4];
        float xv[4] = {v.x, v.y, v.z, v.w};
        int k = k4 * 4;
#pragma unroll
        for (int kk = 0; kk < 4; kk++) {
            const float4* wrow = reinterpret_cast<const float4*>(W1s + (k + kk) * HIDDEN);
            float xs = xv[kk];
#pragma unroll
            for (int h4 = 0; h4 < HIDDEN / 4; h4++) {
                float4 w = wrow[h4];
                h[h4 * 4 + 0] = fmaf(xs, w.x, h[h4 * 4 + 0]);
                h[h4 * 4 + 1] = fmaf(xs, w.y, h[h4 * 4 + 1]);
                h[h4 * 4 + 2] = fmaf(xs, w.z, h[h4 * 4 + 2]);
                h[h4 * 4 + 3] = fmaf(xs, w.w, h[h4 * 4 + 3]);
            }
        }
    }
#pragma unroll
    for (int j = 0; j < HIDDEN; j++) h[j] = fmaxf(h[j], 0.0f);

    // stage 2: out = x + h @ W2 + b2
    const float4* xr = reinterpret_cast<const float4*>(x) + (size_t)n * (IN_DIM / 4);
    float4* outr = reinterpret_cast<float4*>(out) + (size_t)n * (IN_DIM / 4);
#pragma unroll 2
    for (int d4 = 0; d4 < IN_DIM / 4; d4++) {
        float4 s = reinterpret_cast<const float4*>(b2s)[d4];
#pragma unroll
        for (int j = 0; j < HIDDEN; j++) {
            float4 w = reinterpret_cast<const float4*>(W2s + j * IN_DIM)[d4];
            s.x = fmaf(h[j], w.x, s.x);
            s.y = fmaf(h[j], w.y, s.y);
            s.z = fmaf(h[j], w.z, s.z);
            s.w = fmaf(h[j], w.w, s.w);
        }
        float4 xv = xr[d4];
        s.x += xv.x; s.y += xv.y; s.z += xv.z; s.w += xv.w;
        outr[d4] = s;
    }
}

// ---------------------------------------------------------------------------
extern "C" void kernel_launch(void* const* d_in, const int* in_sizes, int n_in,
                              void* d_out, int out_size) {
    const float* x     = (const float*)d_in[0];
    const int*   ei    = (const int*)d_in[1];   // jax canonicalizes int64 -> int32
    const float* W_sim = (const float*)d_in[2];
    const float* b_sim = (const float*)d_in[3];
    const float* w_vec = (const float*)d_in[4];
    const float* b_vec = (const float*)d_in[5];
    const float* W1    = (const float*)d_in[6];
    const float* b1    = (const float*)d_in[7];
    const float* W2    = (const float*)d_in[8];
    const float* b2    = (const float*)d_in[9];
    float* out = (float*)d_out;

    int N = in_sizes[0] / IN_DIM;
    long long E = (long long)in_sizes[1] / 2;

    // zero accumulator + compute gates (independent)
    size_t n4 = (size_t)N * IN_DIM / 4;
    zero_kernel<<<(unsigned)((n4 + 255) / 256), 256>>>(n4);
    gate_kernel<<<(N + 255) / 256, 256>>>(x, W_sim, b_sim, w_vec, b_vec, N);

    // scatter: one warp per edge, 8 warps per block
    int wpb = 256 / 32;
    scatter_kernel<<<(unsigned)((E + wpb - 1) / wpb), 256>>>(x, ei, E);

    // fused MLP + residual
    cudaFuncSetAttribute(mlp_kernel, cudaFuncAttributeMaxDynamicSharedMemorySize, 66432);
    mlp_kernel<<<(N + 255) / 256, 256, 66432>>>(x, W1, b1, W2, b2, out, N);
}

// round 2
// speedup vs baseline: 1.0074x; 1.0074x over previous
#include <cuda_runtime.h>

#define N_NODES 100000
#define IN_DIM 128
#define HIDDEN 64

// Scratch (allocation-guard-safe: __device__ globals)
__device__ float g_weights[N_NODES];
__device__ float g_readout[(size_t)N_NODES * IN_DIM];

// ---------------------------------------------------------------------------
// Kernel 1: per-node gate  weights[n] = sigmoid(tanh(x@W_sim+b_sim)@w_vec+b_vec)
// ---------------------------------------------------------------------------
__global__ void gate_kernel(const float* __restrict__ x,
                            const float* __restrict__ W_sim,
                            const float* __restrict__ b_sim,
                            const float* __restrict__ w_vec,
                            const float* __restrict__ b_vec,
                            int N) {
    __shared__ float Ws[IN_DIM * HIDDEN];   // 32 KB
    __shared__ float bs[HIDDEN];
    __shared__ float wv[HIDDEN];
    __shared__ float bv;
    for (int i = threadIdx.x; i < IN_DIM * HIDDEN; i += blockDim.x) Ws[i] = W_sim[i];
    for (int i = threadIdx.x; i < HIDDEN; i += blockDim.x) { bs[i] = b_sim[i]; wv[i] = w_vec[i]; }
    if (threadIdx.x == 0) bv = b_vec[0];
    __syncthreads();

    int n = blockIdx.x * blockDim.x + threadIdx.x;
    if (n >= N) return;

    float acc[HIDDEN];
#pragma unroll
    for (int h = 0; h < HIDDEN; h++) acc[h] = bs[h];

    const float4* xr = reinterpret_cast<const float4*>(x) + (size_t)n * (IN_DIM / 4);
#pragma unroll 4
    for (int k4 = 0; k4 < IN_DIM / 4; k4++) {
        float4 v = xr[k4];
        float xv[4] = {v.x, v.y, v.z, v.w};
        int k = k4 * 4;
#pragma unroll
        for (int kk = 0; kk < 4; kk++) {
            const float4* wrow = reinterpret_cast<const float4*>(Ws + (k + kk) * HIDDEN);
            float xs = xv[kk];
#pragma unroll
            for (int h4 = 0; h4 < HIDDEN / 4; h4++) {
                float4 w = wrow[h4];
                acc[h4 * 4 + 0] = fmaf(xs, w.x, acc[h4 * 4 + 0]);
                acc[h4 * 4 + 1] = fmaf(xs, w.y, acc[h4 * 4 + 1]);
                acc[h4 * 4 + 2] = fmaf(xs, w.z, acc[h4 * 4 + 2]);
                acc[h4 * 4 + 3] = fmaf(xs, w.w, acc[h4 * 4 + 3]);
            }
        }
    }

    float z = bv;
#pragma unroll
    for (int h = 0; h < HIDDEN; h++) z = fmaf(tanhf(acc[h]), wv[h], z);
    g_weights[n] = 1.0f / (1.0f + expf(-z));
}

// ---------------------------------------------------------------------------
// Kernel 2: zero the readout accumulator (graph replays must be deterministic)
// ---------------------------------------------------------------------------
__global__ void zero_kernel(size_t n4) {
    size_t i = (size_t)blockIdx.x * blockDim.x + threadIdx.x;
    if (i < n4) reinterpret_cast<float4*>(g_readout)[i] = make_float4(0.f, 0.f, 0.f, 0.f);
}

// ---------------------------------------------------------------------------
// Kernel 3: scatter  readout[row] += x[col] * weights[col]   (warp per edge)
// ---------------------------------------------------------------------------
__device__ __forceinline__ void red_add_v4(float* addr, float4 v) {
    asm volatile("red.global.add.v4.f32 [%0], {%1,%2,%3,%4};"
                 :: "l"(addr), "f"(v.x), "f"(v.y), "f"(v.z), "f"(v.w)
                 : "memory");
}

__global__ void scatter_kernel(const float* __restrict__ x,
                               const int* __restrict__ ei,   // [2, E] int32
                               long long E) {
    long long w = (long long)blockIdx.x * (blockDim.x >> 5) + (threadIdx.x >> 5);
    if (w >= E) return;
    int lane = threadIdx.x & 31;
    int row = ei[w];        // destination
    int col = ei[E + w];    // source
    float g = g_weights[col];
    float4 v = reinterpret_cast<const float4*>(x)[(size_t)col * (IN_DIM / 4) + lane];
    v.x *= g; v.y *= g; v.z *= g; v.w *= g;
    float* dst = g_readout + (size_t)row * IN_DIM + lane * 4;
    red_add_v4(dst, v);
}

// ---------------------------------------------------------------------------
// Kernel 4: out = x + relu(readout@W1+b1)@W2 + b2
// ---------------------------------------------------------------------------
__global__ void mlp_kernel(const float* __restrict__ x,
                           const float* __restrict__ W1,
                           const float* __restrict__ b1,
                           const float* __restrict__ W2,
                           const float* __restrict__ b2,
                           float* __restrict__ out, int N) {
    extern __shared__ float smem[];
    float* W1s = smem;                 // 8192 floats
    float* W2s = smem + 8192;          // 8192 floats
    float* b1s = smem + 16384;         // 64
    float* b2s = smem + 16448;         // 128
    for (int i = threadIdx.x; i < 8192; i += blockDim.x) { W1s[i] = W1[i]; W2s[i] = W2[i]; }
    for (int i = threadIdx.x; i < HIDDEN; i += blockDim.x) b1s[i] = b1[i];
    for (int i = threadIdx.x; i < IN_DIM; i += blockDim.x) b2s[i] = b2[i];
    __syncthreads();

    int n = blockIdx.x * blockDim.x + threadIdx.x;
    if (n >= N) return;

    // stage 1: h = relu(readout @ W1 + b1)
    float h[HIDDEN];
#pragma unroll
    for (int j = 0; j < HIDDEN; j++) h[j] = b1s[j];

    const float4* rr = reinterpret_cast<const float4*>(g_readout) + (size_t)n * (IN_DIM / 4);
#pragma unroll 4
    for (int k4 = 0; k4 < IN_DIM / 4; k4++) {
        float4 v = rr[k4];
        float xv[4] = {v.x, v.y, v.z, v.w};
        int k = k4 * 4;
#pragma unroll
        for (int kk = 0; kk < 4; kk++) {
            const float4* wrow = reinterpret_cast<const float4*>(W1s + (k + kk) * HIDDEN);
            float xs = xv[kk];
#pragma unroll
            for (int h4 = 0; h4 < HIDDEN / 4; h4++) {
                float4 w = wrow[h4];
                h[h4 * 4 + 0] = fmaf(xs, w.x, h[h4 * 4 + 0]);
                h[h4 * 4 + 1] = fmaf(xs, w.y, h[h4 * 4 + 1]);
                h[h4 * 4 + 2] = fmaf(xs, w.z, h[h4 * 4 + 2]);
                h[h4 * 4 + 3] = fmaf(xs, w.w, h[h4 * 4 + 3]);
            }
        }
    }
#pragma unroll
    for (int j = 0; j < HIDDEN; j++) h[j] = fmaxf(h[j], 0.0f);

    // stage 2: out = x + h @ W2 + b2
    const float4* xr = reinterpret_cast<const float4*>(x) + (size_t)n * (IN_DIM / 4);
    float4* outr = reinterpret_cast<float4*>(out) + (size_t)n * (IN_DIM / 4);
#pragma unroll 2
    for (int d4 = 0; d4 < IN_DIM / 4; d4++) {
        float4 s = reinterpret_cast<const float4*>(b2s)[d4];
#pragma unroll
        for (int j = 0; j < HIDDEN; j++) {
            float4 w = reinterpret_cast<const float4*>(W2s + j * IN_DIM)[d4];
            s.x = fmaf(h[j], w.x, s.x);
            s.y = fmaf(h[j], w.y, s.y);
            s.z = fmaf(h[j], w.z, s.z);
            s.w = fmaf(h[j], w.w, s.w);
        }
        float4 xv = xr[d4];
        s.x += xv.x; s.y += xv.y; s.z += xv.z; s.w += xv.w;
        outr[d4] = s;
    }
}

// ---------------------------------------------------------------------------
extern "C" void kernel_launch(void* const* d_in, const int* in_sizes, int n_in,
                              void* d_out, int out_size) {
    const float* x     = (const float*)d_in[0];
    const int*   ei    = (const int*)d_in[1];   // jax canonicalizes int64 -> int32
    const float* W_sim = (const float*)d_in[2];
    const float* b_sim = (const float*)d_in[3];
    const float* w_vec = (const float*)d_in[4];
    const float* b_vec = (const float*)d_in[5];
    const float* W1    = (const float*)d_in[6];
    const float* b1    = (const float*)d_in[7];
    const float* W2    = (const float*)d_in[8];
    const float* b2    = (const float*)d_in[9];
    float* out = (float*)d_out;

    int N = in_sizes[0] / IN_DIM;
    long long E = (long long)in_sizes[1] / 2;

    // zero accumulator + compute gates (independent)
    size_t n4 = (size_t)N * IN_DIM / 4;
    zero_kernel<<<(unsigned)((n4 + 255) / 256), 256>>>(n4);
    gate_kernel<<<(N + 255) / 256, 256>>>(x, W_sim, b_sim, w_vec, b_vec, N);

    // scatter: one warp per edge, 8 warps per block
    int wpb = 256 / 32;
    scatter_kernel<<<(unsigned)((E + wpb - 1) / wpb), 256>>>(x, ei, E);

    // fused MLP + residual
    cudaFuncSetAttribute(mlp_kernel, cudaFuncAttributeMaxDynamicSharedMemorySize, 66432);
    mlp_kernel<<<(N + 255) / 256, 256, 66432>>>(x, W1, b1, W2, b2, out, N);
}